// round 7
// baseline (speedup 1.0000x reference)
#include <cuda_runtime.h>
#include <math.h>

// ---------------- static scratch ----------------
#define SMAX   65
#define NMAXV  (SMAX*SMAX*SMAX)       // 274625 vertices
#define NWPAD  8832                   // occ bit-words + pad for max offset reads
#define NGMAX  9216                   // 32-anchor edge groups (padded)
#define NCMAX  (64*64*64)             // cubes
#define TMAXT  (6*NCMAX)              // tets
#define MAXCH  1024
#define MID_IT 9                      // ceil(NGMAX/1024)
#define TSI    8
#define TCH    (1024*TSI)             // tets per scan chunk (8192)
#define SPIN_MAX (1u<<24)             // bounded spin: fail loud, never hang

__device__ unsigned           g_occw[NWPAD];      // bit-packed occupancy (pad stays 0)
__device__ float              g_sdf[NMAXV];       // tanh(sdf)
__device__ float              g_rot[3*NMAXV];     // scale * R^T @ [d0,d1,1]
__device__ uint4              g_egrp[NGMAX*2];    // per group: 7 masks + exclusive base
__device__ int                g_eGrpCnt[NGMAX];
__device__ unsigned char      g_cubeCode[NCMAX];  // 8-bit corner occupancy per cube
__device__ unsigned           g_tetScan[TMAXT];   // packed (cnt1 lo16 | cnt2 hi16) local scan
__device__ unsigned           g_tBlkP[MAXCH];     // packed per-chunk sums
__device__ unsigned long long g_tBlk64[MAXCH];    // widened exclusive chunk offsets
__device__ int                g_nv;               // total crossing edges (= output verts)
__device__ int                g_n1;               // total 1-triangle tets

// grid barrier state (monotonic epoch; g_cnt reset each launch by last arriver)
__device__ unsigned           g_cnt;
__device__ volatile unsigned  g_epoch;

__constant__ int c_path[6][4] = {
    {0,4,6,7},{0,4,5,7},{0,2,6,7},{0,2,3,7},{0,1,5,7},{0,1,3,7}};
__constant__ int c_ntri[16] = {0,1,1,2,1,2,2,1,1,2,2,1,2,1,1,0};
__constant__ int c_tri[16][6] = {
    {-1,-1,-1,-1,-1,-1},
    { 1, 0, 2,-1,-1,-1},
    { 4, 0, 3,-1,-1,-1},
    { 1, 4, 2, 1, 3, 4},
    { 3, 1, 5,-1,-1,-1},
    { 2, 3, 0, 2, 5, 3},
    { 1, 4, 0, 1, 5, 4},
    { 4, 2, 5,-1,-1,-1},
    { 4, 5, 2,-1,-1,-1},
    { 4, 1, 0, 4, 5, 1},
    { 3, 2, 0, 3, 5, 2},
    { 1, 3, 5,-1,-1,-1},
    { 4, 1, 2, 4, 3, 1},
    { 3, 0, 4,-1,-1,-1},
    { 2, 0, 1,-1,-1,-1},
    {-1,-1,-1,-1,-1,-1}};

__device__ __forceinline__ unsigned bits32(int b)
{
    unsigned w0 = g_occw[b >> 5];
    unsigned w1 = g_occw[(b >> 5) + 1];
    return __funnelshift_r(w0, w1, b & 31);
}

// grid-wide barrier i (i = 1..nbar); epoch-based, replay-safe, bounded spin.
__device__ __forceinline__ void gbar(unsigned e0, unsigned i, unsigned nb, bool last)
{
    __threadfence();
    __syncthreads();
    if (threadIdx.x == 0) {
        unsigned prev = atomicAdd(&g_cnt, 1u);
        if (prev == i*nb - 1u) {          // last arriver of this barrier
            if (last) g_cnt = 0u;         // reset for next launch
            __threadfence();
            g_epoch = e0 + i;
        } else {
            unsigned spins = 0u;
            while ((unsigned)(g_epoch - e0) < i) {
                if (++spins > SPIN_MAX) break;    // FAIL LOUD: proceed, results wrong
            }
            __threadfence();
        }
    }
    __syncthreads();
}

// shuffle-based exclusive block scan (u32). ALL 32 lanes of warp 0 run the
// reduction shuffles (partial-warp shuffle with full mask hangs). Trailing
// sync so it is safe in a loop.
template<int NT>
__device__ __forceinline__ unsigned blk_exscan_u32(unsigned v, int tid, unsigned* tot)
{
    constexpr int NW = NT/32;
    __shared__ unsigned ws[NW];
    int lane = tid & 31, w = tid >> 5;
    unsigned x = v;
#pragma unroll
    for (int o = 1; o < 32; o <<= 1) {
        unsigned y = __shfl_up_sync(0xffffffffu, x, o);
        if (lane >= o) x += y;
    }
    if (lane == 31) ws[w] = x;
    __syncthreads();
    if (w == 0) {
        unsigned t = (lane < NW) ? ws[lane] : 0u;
#pragma unroll
        for (int o = 1; o < NW; o <<= 1) {
            unsigned y = __shfl_up_sync(0xffffffffu, t, o);
            if (lane >= o) t += y;
        }
        if (lane < NW) ws[lane] = t;
    }
    __syncthreads();
    unsigned base = w ? ws[w-1] : 0u;
    *tot = ws[NW - 1];
    __syncthreads();
    return base + x - v;
}

template<int NT>
__device__ __forceinline__ unsigned long long blk_exscan_u64(unsigned long long v, int tid,
                                                             unsigned long long* tot)
{
    constexpr int NW = NT/32;
    __shared__ unsigned long long ws[NW];
    int lane = tid & 31, w = tid >> 5;
    unsigned long long x = v;
#pragma unroll
    for (int o = 1; o < 32; o <<= 1) {
        unsigned long long y = __shfl_up_sync(0xffffffffu, x, o);
        if (lane >= o) x += y;
    }
    if (lane == 31) ws[w] = x;
    __syncthreads();
    if (w == 0) {
        unsigned long long t = (lane < NW) ? ws[lane] : 0ull;
#pragma unroll
        for (int o = 1; o < NW; o <<= 1) {
            unsigned long long y = __shfl_up_sync(0xffffffffu, t, o);
            if (lane >= o) t += y;
        }
        if (lane < NW) ws[lane] = t;
    }
    __syncthreads();
    unsigned long long base = w ? ws[w-1] : 0ull;
    *tot = ws[NW - 1];
    __syncthreads();
    return base + x - v;
}

// ---------------- the whole pipeline, one persistent kernel ----------------
__global__ void __launch_bounds__(1024, 1)
k_all(const float* __restrict__ feats, const float* __restrict__ sdf_n,
      const float* __restrict__ dir,   const float* __restrict__ rotm,
      const float* __restrict__ scales, float* __restrict__ out,
      int N, int S, int R, int NG, int NC, int T, int nCh, int E, float dscale)
{
    int tid  = threadIdx.x;
    int bid  = blockIdx.x;
    unsigned nb = gridDim.x;
    int P    = (int)nb * 1024;
    int gtid = bid*1024 + tid;
    int S2 = S*S, R2 = R*R, R3 = R2*R;

    __shared__ unsigned s_e0;
    if (tid == 0) s_e0 = g_epoch;
    __syncthreads();
    unsigned e0 = s_e0;

    // ======== phase A: per-vertex prep + occ bit-pack ========
    int Npad = (N + 31) & ~31;
    for (int v = gtid; v < Npad; v += P) {
        bool inb = v < N;
        float s = inb ? sdf_n[v] : -1.0f;
        unsigned bal = __ballot_sync(0xffffffffu, s > 0.0f);
        if ((v & 31) == 0) g_occw[v >> 5] = bal;
        if (inb) {
            g_sdf[v] = tanhf(s);
            float l0 = dscale * tanhf(dir[2*v+0]);
            float l1 = dscale * tanhf(dir[2*v+1]);
            const float* m = rotm + 9*(size_t)v;
            float sc = scales[v];
            g_rot[3*v+0] = (m[0]*l0 + m[3]*l1 + m[6]) * sc;
            g_rot[3*v+1] = (m[1]*l0 + m[4]*l1 + m[7]) * sc;
            g_rot[3*v+2] = (m[2]*l0 + m[5]*l1 + m[8]) * sc;
        }
    }
    gbar(e0, 1, nb, false);

    // ======== phase B: edge-group masks + counts, cube codes ========
    for (int t = gtid; t < NG; t += P) {
        int v0 = t << 5;
        int i0 = v0 / S2; int rem = v0 - i0*S2; int j0 = rem / S; int k0 = rem - j0*S;
        int qw = S - k0;
        unsigned pre = (qw >= 32) ? 0xffffffffu : ((1u << (qw & 31)) - 1u);
        int j1 = j0 + 1, i1 = i0; if (j1 == S) { j1 = 0; ++i1; }
        int nvld = N - v0;
        unsigned tailm = (nvld >= 32) ? 0xffffffffu : ((1u << (nvld & 31)) - 1u);
        unsigned A = bits32(v0);
        unsigned mm[7]; int cnt = 0;
#pragma unroll
        for (int tt = 1; tt <= 7; ++tt) {
            int di = (tt>>2)&1, dj = (tt>>1)&1, dk = tt&1;
            int d = di*S2 + dj*S + dk;
            unsigned X = A ^ bits32(v0 + d);
            unsigned vm = (((i0+di < S) && (j0+dj < S)) ? pre : 0u)
                        | (((i1+di < S) && (j1+dj < S)) ? ~pre : 0u);
            if (dk && (qw - 1) < 32) vm &= ~(1u << (qw - 1));
            vm &= tailm;
            mm[tt-1] = X & vm;
            cnt += __popc(mm[tt-1]);
        }
        g_egrp[2*t]   = make_uint4(mm[0], mm[1], mm[2], mm[3]);
        g_egrp[2*t+1] = make_uint4(mm[4], mm[5], mm[6], 0u);
        g_eGrpCnt[t]  = cnt;
    }
    for (int c = gtid; c < NC; c += P) {
        int i = c / R2; int rem = c - i*R2; int j = rem / R; int k = rem - j*R;
        int b = (i*S + j)*S + k;
        unsigned p00 = bits32(b)          & 3u;
        unsigned p01 = bits32(b + S)      & 3u;
        unsigned p10 = bits32(b + S2)     & 3u;
        unsigned p11 = bits32(b + S2 + S) & 3u;
        g_cubeCode[c] = (unsigned char)(p00 | (p01 << 2) | (p10 << 4) | (p11 << 6));
    }
    gbar(e0, 2, nb, false);

    // ======== phase C: tet classify + per-chunk packed scan ========
    for (int ch = bid; ch < nCh; ch += (int)nb) {
        int base = ch*TCH + tid*TSI;
        unsigned loc[TSI], sum = 0u;
#pragma unroll
        for (int it = 0; it < TSI; ++it) {
            int r = base + it;
            unsigned add = 0u;
            if (r < T) {
                int p = r / R3, c = r - p*R3;
                unsigned code = g_cubeCode[c];
                int ti = ((code >> c_path[p][0]) & 1)
                       | (((code >> c_path[p][1]) & 1) << 1)
                       | (((code >> c_path[p][2]) & 1) << 2)
                       | (((code >> c_path[p][3]) & 1) << 3);
                int nt = c_ntri[ti];
                add = (nt == 1) ? 1u : ((nt == 2) ? 0x10000u : 0u);
            }
            loc[it] = sum; sum += add;
        }
        unsigned tot;
        unsigned exc = blk_exscan_u32<1024>(sum, tid, &tot);
#pragma unroll
        for (int it = 0; it < TSI; ++it) {
            int r = base + it;
            if (r < T) g_tetScan[r] = exc + loc[it];
        }
        if (tid == 1023) g_tBlkP[ch] = tot;
    }
    gbar(e0, 3, nb, false);

    // ======== phase D: mid-level scans (blocks 0 and 1 only) ========
    if (bid == 0) {
        int base = tid * MID_IT;
        int loc[MID_IT]; int sum = 0;
#pragma unroll
        for (int it = 0; it < MID_IT; ++it) {
            int idx = base + it;
            int v = (idx < NG) ? g_eGrpCnt[idx] : 0;
            loc[it] = sum; sum += v;
        }
        unsigned tot;
        unsigned exc = blk_exscan_u32<1024>((unsigned)sum, tid, &tot);
#pragma unroll
        for (int it = 0; it < MID_IT; ++it) {
            int idx = base + it;
            if (idx < NG) ((unsigned*)g_egrp)[idx*8 + 7] = exc + (unsigned)loc[it];
        }
        if (tid == 0) g_nv = (int)tot;
    } else if (bid == 1) {
        unsigned long long v = 0ull;
        if (tid < nCh) {
            unsigned pkt = g_tBlkP[tid];
            v = (unsigned long long)(pkt & 0xffffu)
              | ((unsigned long long)(pkt >> 16) << 32);
        }
        unsigned long long tot;
        unsigned long long exc = blk_exscan_u64<1024>(v, tid, &tot);
        if (tid < nCh) g_tBlk64[tid] = exc;
        if (tid == 0) g_n1 = (int)(tot & 0xffffffffull);
    }
    gbar(e0, 4, nb, true);

    // ======== phase E: emit vertex features + faces ========
    size_t vbase = (size_t)g_nv * 6;
    int n1 = g_n1;

    for (int e = gtid; e < E; e += P) {
        int v = e / 7;
        int tt = e - 7*v + 1;
        int g = v >> 5, q = v & 31;
        uint4 Aa = g_egrp[2*g], Bb = g_egrp[2*g+1];
        unsigned mm[7] = {Aa.x, Aa.y, Aa.z, Aa.w, Bb.x, Bb.y, Bb.z};
        int tm = tt - 1;
        if (!((mm[tm] >> q) & 1u)) continue;

        unsigned low = (1u << q) - 1u;
        int rank = (int)Bb.w;
#pragma unroll
        for (int x = 0; x < 7; ++x) rank += __popc(mm[x] & low);
#pragma unroll
        for (int x = 0; x < 6; ++x) if (x < tm) rank += (mm[x] >> q) & 1u;

        int v2 = v + ((tt>>2)&1)*S2 + ((tt>>1)&1)*S + (tt&1);
        float sa = g_sdf[v], sb = g_sdf[v2];
        float inv = 1.0f / (sa - sb);
        float wa = -sb * inv, wb = sa * inv;
        float* o = out + (size_t)rank * 6;
        o[0] = wa*g_rot[3*v+0] + wb*g_rot[3*v2+0];
        o[1] = wa*g_rot[3*v+1] + wb*g_rot[3*v2+1];
        o[2] = wa*g_rot[3*v+2] + wb*g_rot[3*v2+2];
        const float* fa = feats + (size_t)v  * 6 + 3;
        const float* fb = feats + (size_t)v2 * 6 + 3;
        o[3] = wa*fa[0] + wb*fb[0];
        o[4] = wa*fa[1] + wb*fb[1];
        o[5] = wa*fa[2] + wb*fb[2];
    }

    for (int r = gtid; r < T; r += P) {
        int p = r / R3, c = r - p*R3;
        unsigned code = g_cubeCode[c];
        int P0 = c_path[p][0], P1 = c_path[p][1], P2 = c_path[p][2], P3 = c_path[p][3];
        int ti = ((code >> P0) & 1) | (((code >> P1) & 1) << 1)
               | (((code >> P2) & 1) << 2) | (((code >> P3) & 1) << 3);
        int nt = c_ntri[ti];
        if (!nt) continue;

        int i = c / R2; int rem = c - i*R2; int j = rem / R; int k = rem - j*R;
        int v000 = (i*S + j)*S + k;
        int PP[4] = {P0, P1, P2, P3};
        const int ea[6] = {0,0,0,1,1,2};
        const int eb[6] = {1,2,3,2,3,3};
        int er[6];
#pragma unroll
        for (int s = 0; s < 6; ++s) {
            int na = PP[ea[s]], nbn = PP[eb[s]];
            int va = v000 + ((na>>2)&1)*S2 + ((na>>1)&1)*S + (na&1);
            int tc = na ^ nbn;
            int gg = va >> 5, qq = va & 31;
            uint4 Aa = g_egrp[2*gg], Bb = g_egrp[2*gg+1];
            unsigned mm[7] = {Aa.x, Aa.y, Aa.z, Aa.w, Bb.x, Bb.y, Bb.z};
            unsigned low = (1u << qq) - 1u;
            int rk = (int)Bb.w;
#pragma unroll
            for (int x = 0; x < 7; ++x) rk += __popc(mm[x] & low);
            int tmc = tc - 1;
#pragma unroll
            for (int x = 0; x < 6; ++x) if (x < tmc) rk += (mm[x] >> qq) & 1u;
            er[s] = rk;
        }

        unsigned sc = g_tetScan[r];
        unsigned long long bk = g_tBlk64[r / TCH];
        int s1 = (int)(sc & 0xffffu) + (int)(unsigned)(bk & 0xffffffffull);
        int s2 = (int)(sc >> 16)     + (int)(unsigned)(bk >> 32);
        const int* tt = c_tri[ti];

        if (nt == 1) {
            size_t o = vbase + (size_t)s1 * 3;
            out[o+0] = (float)er[tt[0]];
            out[o+1] = (float)er[tt[1]];
            out[o+2] = (float)er[tt[2]];
        } else {
            size_t o = vbase + ((size_t)n1 + 2*(size_t)s2) * 3;
#pragma unroll
            for (int q = 0; q < 6; ++q)
                out[o+q] = (float)er[tt[q]];
        }
    }
}

// ---------------- launch ----------------
extern "C" void kernel_launch(void* const* d_in, const int* in_sizes, int n_in,
                              void* d_out, int out_size)
{
    const float* feats  = (const float*)d_in[0];
    const float* sdf_n  = (const float*)d_in[1];
    const float* dir    = (const float*)d_in[2];
    const float* rotm   = (const float*)d_in[3];
    const float* scales = (const float*)d_in[4];

    int N = in_sizes[1];
    int S = 1;
    while ((long long)S*S*S < (long long)N) ++S;   // S = R+1
    int R = S - 1;
    int E = 7*N;
    int T = 6*R*R*R;
    int NC = R*R*R;
    int NG = (N + 31) >> 5;
    int nCh = (T + TCH - 1) / TCH;
    float dscale = 4.0f / (float)R;
    float* out = (float*)d_out;

    int dev = 0;
    cudaGetDevice(&dev);
    int sms = 148;
    cudaDeviceGetAttribute(&sms, cudaDevAttrMultiProcessorCount, dev);
    int occ = 1;
    cudaOccupancyMaxActiveBlocksPerMultiprocessor(&occ, k_all, 1024, 0);
    if (occ < 1) occ = 1;
    int grid = sms * occ;

    k_all<<<grid, 1024>>>(feats, sdf_n, dir, rotm, scales, out,
                          N, S, R, NG, NC, T, nCh, E, dscale);
}

// round 8
// speedup vs baseline: 1.1432x; 1.1432x over previous
#include <cuda_runtime.h>
#include <math.h>

// ---------------- static scratch ----------------
#define SMAX   65
#define NMAXV  (SMAX*SMAX*SMAX)       // 274625 vertices
#define NWPAD  8832                   // occ bit-words + pad
#define NGMAX  9216                   // 32-anchor edge groups (padded)
#define NCMAX  (64*64*64)             // cubes
#define TMAXT  (6*NCMAX)              // tets
#define SCAN_B 256
#define SCAN_I 8
#define TCH    (SCAN_B*SCAN_I)        // 2048 tets per chunk
#define MAXCH  1024

__device__ unsigned           g_occw[NWPAD];
__device__ float              g_sdf[NMAXV];
__device__ float              g_rot[3*NMAXV];
__device__ uint4              g_egrp[NGMAX*2];    // 7 masks + exclusive base
__device__ int                g_eGrpCnt[NGMAX];
__device__ unsigned char      g_cubeCode[NCMAX];
__device__ unsigned           g_tetScan[TMAXT];   // packed (cnt1 lo16 | cnt2 hi16)
__device__ unsigned           g_tBlkP[MAXCH];
__device__ unsigned long long g_tBlk64[MAXCH];
__device__ int                g_nv;
__device__ int                g_n1;
__device__ unsigned           g_done1;            // last-block counters (self-reset)
__device__ unsigned           g_done2;

__constant__ int c_path[6][4] = {
    {0,4,6,7},{0,4,5,7},{0,2,6,7},{0,2,3,7},{0,1,5,7},{0,1,3,7}};
__constant__ int c_ntri[16] = {0,1,1,2,1,2,2,1,1,2,2,1,2,1,1,0};
__constant__ int c_tri[16][6] = {
    {-1,-1,-1,-1,-1,-1},
    { 1, 0, 2,-1,-1,-1},
    { 4, 0, 3,-1,-1,-1},
    { 1, 4, 2, 1, 3, 4},
    { 3, 1, 5,-1,-1,-1},
    { 2, 3, 0, 2, 5, 3},
    { 1, 4, 0, 1, 5, 4},
    { 4, 2, 5,-1,-1,-1},
    { 4, 5, 2,-1,-1,-1},
    { 4, 1, 0, 4, 5, 1},
    { 3, 2, 0, 3, 5, 2},
    { 1, 3, 5,-1,-1,-1},
    { 4, 1, 2, 4, 3, 1},
    { 3, 0, 4,-1,-1,-1},
    { 2, 0, 1,-1,-1,-1},
    {-1,-1,-1,-1,-1,-1}};

__device__ __forceinline__ unsigned bits32(int b)
{
    unsigned w0 = g_occw[b >> 5];
    unsigned w1 = g_occw[(b >> 5) + 1];
    return __funnelshift_r(w0, w1, b & 31);
}

// shuffle-based exclusive block scan; ALL 32 lanes of warp 0 run the reduction
// shuffles (partial-warp shuffle with full mask hangs). Trailing sync: loop-safe.
template<int NT>
__device__ __forceinline__ unsigned blk_exscan_u32(unsigned v, int tid, unsigned* tot)
{
    constexpr int NW = NT/32;
    __shared__ unsigned ws[NW];
    int lane = tid & 31, w = tid >> 5;
    unsigned x = v;
#pragma unroll
    for (int o = 1; o < 32; o <<= 1) {
        unsigned y = __shfl_up_sync(0xffffffffu, x, o);
        if (lane >= o) x += y;
    }
    if (lane == 31) ws[w] = x;
    __syncthreads();
    if (w == 0) {
        unsigned t = (lane < NW) ? ws[lane] : 0u;
#pragma unroll
        for (int o = 1; o < NW; o <<= 1) {
            unsigned y = __shfl_up_sync(0xffffffffu, t, o);
            if (lane >= o) t += y;
        }
        if (lane < NW) ws[lane] = t;
    }
    __syncthreads();
    unsigned base = w ? ws[w-1] : 0u;
    *tot = ws[NW - 1];
    __syncthreads();
    return base + x - v;
}

template<int NT>
__device__ __forceinline__ unsigned long long blk_exscan_u64(unsigned long long v, int tid,
                                                             unsigned long long* tot)
{
    constexpr int NW = NT/32;
    __shared__ unsigned long long ws[NW];
    int lane = tid & 31, w = tid >> 5;
    unsigned long long x = v;
#pragma unroll
    for (int o = 1; o < 32; o <<= 1) {
        unsigned long long y = __shfl_up_sync(0xffffffffu, x, o);
        if (lane >= o) x += y;
    }
    if (lane == 31) ws[w] = x;
    __syncthreads();
    if (w == 0) {
        unsigned long long t = (lane < NW) ? ws[lane] : 0ull;
#pragma unroll
        for (int o = 1; o < NW; o <<= 1) {
            unsigned long long y = __shfl_up_sync(0xffffffffu, t, o);
            if (lane >= o) t += y;
        }
        if (lane < NW) ws[lane] = t;
    }
    __syncthreads();
    unsigned long long base = w ? ws[w-1] : 0ull;
    *tot = ws[NW - 1];
    __syncthreads();
    return base + x - v;
}

// last-block-done: returns true in exactly one block after all blocks arrive.
__device__ __forceinline__ bool last_block(unsigned* ctr, unsigned nb)
{
    __shared__ unsigned s_last;
    __threadfence();
    __syncthreads();
    if (threadIdx.x == 0) {
        unsigned prev = atomicAdd(ctr, 1u);
        if (prev == nb - 1u) { *ctr = 0u; s_last = 1u; }   // self-reset for replay
        else                 s_last = 0u;
    }
    __syncthreads();
    return s_last != 0u;
}

// ---------------- kernel 1: per-vertex prep + occ bit-pack ----------------
__global__ void k_prep(const float* __restrict__ sdf_n,
                       const float* __restrict__ dir,
                       const float* __restrict__ rotm,
                       const float* __restrict__ scales,
                       int N, float dscale)
{
    int v = blockIdx.x*blockDim.x + threadIdx.x;
    bool inb = v < N;
    float s = inb ? sdf_n[v] : -1.0f;
    unsigned bal = __ballot_sync(0xffffffffu, s > 0.0f);
    if ((threadIdx.x & 31) == 0) g_occw[v >> 5] = bal;
    if (!inb) return;

    g_sdf[v] = tanhf(s);
    float l0 = dscale * tanhf(dir[2*v+0]);
    float l1 = dscale * tanhf(dir[2*v+1]);
    const float* m = rotm + 9*(size_t)v;
    float sc = scales[v];
    g_rot[3*v+0] = (m[0]*l0 + m[3]*l1 + m[6]) * sc;
    g_rot[3*v+1] = (m[1]*l0 + m[4]*l1 + m[7]) * sc;
    g_rot[3*v+2] = (m[2]*l0 + m[5]*l1 + m[8]) * sc;
}

// ---------------- kernel 2: masks + counts + cube codes; last block scans ----------------
__global__ void k_grp(int N, int S, int NG, int NC, int R)
{
    int t = blockIdx.x*blockDim.x + threadIdx.x;
    int S2 = S*S;

    if (t < NG) {
        int v0 = t << 5;
        int i0 = v0 / S2; int rem = v0 - i0*S2; int j0 = rem / S; int k0 = rem - j0*S;
        int qw = S - k0;
        unsigned pre = (qw >= 32) ? 0xffffffffu : ((1u << (qw & 31)) - 1u);
        int j1 = j0 + 1, i1 = i0; if (j1 == S) { j1 = 0; ++i1; }
        int nvld = N - v0;
        unsigned tailm = (nvld >= 32) ? 0xffffffffu : ((1u << (nvld & 31)) - 1u);
        unsigned A = bits32(v0);
        unsigned mm[7]; int cnt = 0;
#pragma unroll
        for (int tt = 1; tt <= 7; ++tt) {
            int di = (tt>>2)&1, dj = (tt>>1)&1, dk = tt&1;
            int d = di*S2 + dj*S + dk;
            unsigned X = A ^ bits32(v0 + d);
            unsigned vm = (((i0+di < S) && (j0+dj < S)) ? pre : 0u)
                        | (((i1+di < S) && (j1+dj < S)) ? ~pre : 0u);
            if (dk && (qw - 1) < 32) vm &= ~(1u << (qw - 1));
            vm &= tailm;
            mm[tt-1] = X & vm;
            cnt += __popc(mm[tt-1]);
        }
        g_egrp[2*t]   = make_uint4(mm[0], mm[1], mm[2], mm[3]);
        g_egrp[2*t+1] = make_uint4(mm[4], mm[5], mm[6], 0u);
        g_eGrpCnt[t]  = cnt;
    }

    if (t < NC) {
        int R2 = R*R;
        int i = t / R2; int rem = t - i*R2; int j = rem / R; int k = rem - j*R;
        int b = (i*S + j)*S + k;
        unsigned p00 = bits32(b)          & 3u;
        unsigned p01 = bits32(b + S)      & 3u;
        unsigned p10 = bits32(b + S2)     & 3u;
        unsigned p11 = bits32(b + S2 + S) & 3u;
        g_cubeCode[t] = (unsigned char)(p00 | (p01 << 2) | (p10 << 4) | (p11 << 6));
    }

    // last arriving block: exclusive scan over group counts (L2-hot)
    if (last_block(&g_done1, gridDim.x)) {
        int tid = threadIdx.x;
        int K = (NG + SCAN_B - 1) / SCAN_B;       // groups per thread
        int base = tid * K;
        int run = 0;
        // local serial scan into registers via second pass (avoid big local array)
        for (int it = 0; it < K; ++it) {
            int idx = base + it;
            if (idx < NG) run += g_eGrpCnt[idx];
        }
        unsigned tot;
        unsigned exc = blk_exscan_u32<SCAN_B>((unsigned)run, tid, &tot);
        int acc = (int)exc;
        for (int it = 0; it < K; ++it) {
            int idx = base + it;
            if (idx < NG) {
                int c = g_eGrpCnt[idx];
                ((unsigned*)g_egrp)[idx*8 + 7] = (unsigned)acc;
                acc += c;
            }
        }
        if (tid == 0) g_nv = (int)tot;
    }
}

// ---------------- kernel 3: tet classify + chunk scan; last block scans chunks ----------------
__global__ void k_tscan(int T, int R, int nCh)
{
    int tid = threadIdx.x;
    int base = blockIdx.x*TCH + tid*SCAN_I;
    int R3 = R*R*R;
    unsigned loc[SCAN_I], sum = 0u;
#pragma unroll
    for (int it = 0; it < SCAN_I; ++it) {
        int r = base + it;
        unsigned add = 0u;
        if (r < T) {
            int p = r / R3, c = r - p*R3;
            unsigned code = g_cubeCode[c];
            int ti = ((code >> c_path[p][0]) & 1)
                   | (((code >> c_path[p][1]) & 1) << 1)
                   | (((code >> c_path[p][2]) & 1) << 2)
                   | (((code >> c_path[p][3]) & 1) << 3);
            int nt = c_ntri[ti];
            add = (nt == 1) ? 1u : ((nt == 2) ? 0x10000u : 0u);
        }
        loc[it] = sum; sum += add;
    }
    unsigned tot;
    unsigned exc = blk_exscan_u32<SCAN_B>(sum, tid, &tot);
#pragma unroll
    for (int it = 0; it < SCAN_I; ++it) {
        int r = base + it;
        if (r < T) g_tetScan[r] = exc + loc[it];
    }
    if (tid == SCAN_B-1) g_tBlkP[blockIdx.x] = tot;

    // last arriving block: exclusive scan of chunk sums (u64, widened)
    if (last_block(&g_done2, gridDim.x)) {
        int K = (nCh + SCAN_B - 1) / SCAN_B;
        int b0 = tid * K;
        unsigned long long run = 0ull;
        for (int it = 0; it < K; ++it) {
            int idx = b0 + it;
            if (idx < nCh) {
                unsigned pkt = g_tBlkP[idx];
                run += (unsigned long long)(pkt & 0xffffu)
                     + ((unsigned long long)(pkt >> 16) << 32);
            }
        }
        unsigned long long tot64;
        unsigned long long exc64 = blk_exscan_u64<SCAN_B>(run, tid, &tot64);
        unsigned long long acc = exc64;
        for (int it = 0; it < K; ++it) {
            int idx = b0 + it;
            if (idx < nCh) {
                unsigned pkt = g_tBlkP[idx];
                g_tBlk64[idx] = acc;
                acc += (unsigned long long)(pkt & 0xffffu)
                     + ((unsigned long long)(pkt >> 16) << 32);
            }
        }
        if (tid == 0) g_n1 = (int)(tot64 & 0xffffffffull);
    }
}

// ---------------- rank lookup via group masks ----------------
__device__ __forceinline__ int edge_rank(int va, int tc /*1..7*/)
{
    int g = va >> 5, q = va & 31;
    uint4 Aa = g_egrp[2*g], Bb = g_egrp[2*g+1];
    unsigned mm[7] = {Aa.x, Aa.y, Aa.z, Aa.w, Bb.x, Bb.y, Bb.z};
    unsigned low = (1u << q) - 1u;
    int rk = (int)Bb.w;
#pragma unroll
    for (int x = 0; x < 7; ++x) rk += __popc(mm[x] & low);
    int tm = tc - 1;
#pragma unroll
    for (int x = 0; x < 6; ++x) if (x < tm) rk += (mm[x] >> q) & 1u;
    return rk;
}

// ---------------- kernel 4: fused emit (verts then faces) ----------------
__global__ void k_emit(const float* __restrict__ feats, float* __restrict__ out,
                       int E, int T, int R, int S)
{
    int idx = blockIdx.x*blockDim.x + threadIdx.x;
    int S2 = S*S;

    if (idx < E) {
        int e = idx;
        int v = e / 7;
        int tt = e - 7*v + 1;
        int g = v >> 5, q = v & 31;
        uint4 Aa = g_egrp[2*g], Bb = g_egrp[2*g+1];
        unsigned mm[7] = {Aa.x, Aa.y, Aa.z, Aa.w, Bb.x, Bb.y, Bb.z};
        int tm = tt - 1;
        if (!((mm[tm] >> q) & 1u)) return;

        unsigned low = (1u << q) - 1u;
        int rank = (int)Bb.w;
#pragma unroll
        for (int x = 0; x < 7; ++x) rank += __popc(mm[x] & low);
#pragma unroll
        for (int x = 0; x < 6; ++x) if (x < tm) rank += (mm[x] >> q) & 1u;

        int v2 = v + ((tt>>2)&1)*S2 + ((tt>>1)&1)*S + (tt&1);
        float sa = g_sdf[v], sb = g_sdf[v2];
        float inv = 1.0f / (sa - sb);
        float wa = -sb * inv, wb = sa * inv;
        float* o = out + (size_t)rank * 6;
        o[0] = wa*g_rot[3*v+0] + wb*g_rot[3*v2+0];
        o[1] = wa*g_rot[3*v+1] + wb*g_rot[3*v2+1];
        o[2] = wa*g_rot[3*v+2] + wb*g_rot[3*v2+2];
        const float* fa = feats + (size_t)v  * 6 + 3;
        const float* fb = feats + (size_t)v2 * 6 + 3;
        o[3] = wa*fa[0] + wb*fb[0];
        o[4] = wa*fa[1] + wb*fb[1];
        o[5] = wa*fa[2] + wb*fb[2];
        return;
    }

    int r = idx - E;
    if (r >= T) return;
    int R3 = R*R*R, R2 = R*R;
    int p = r / R3, c = r - p*R3;
    unsigned code = g_cubeCode[c];
    int P0 = c_path[p][0], P1 = c_path[p][1], P2 = c_path[p][2], P3 = c_path[p][3];
    int ti = ((code >> P0) & 1) | (((code >> P1) & 1) << 1)
           | (((code >> P2) & 1) << 2) | (((code >> P3) & 1) << 3);
    int nt = c_ntri[ti];
    if (!nt) return;

    int i = c / R2; int rem = c - i*R2; int j = rem / R; int k = rem - j*R;
    int v000 = (i*S + j)*S + k;
    int PP[4] = {P0, P1, P2, P3};
    const int ea[6] = {0,0,0,1,1,2};
    const int eb[6] = {1,2,3,2,3,3};
    int er[6];
#pragma unroll
    for (int s = 0; s < 6; ++s) {
        int na = PP[ea[s]], nbn = PP[eb[s]];
        int va = v000 + ((na>>2)&1)*S2 + ((na>>1)&1)*S + (na&1);
        er[s] = edge_rank(va, na ^ nbn);
    }

    unsigned sc = g_tetScan[r];
    unsigned long long bk = g_tBlk64[r / TCH];
    int s1 = (int)(sc & 0xffffu) + (int)(unsigned)(bk & 0xffffffffull);
    int s2 = (int)(sc >> 16)     + (int)(unsigned)(bk >> 32);
    size_t vbase = (size_t)g_nv * 6;
    const int* tt = c_tri[ti];

    if (nt == 1) {
        size_t o = vbase + (size_t)s1 * 3;
        out[o+0] = (float)er[tt[0]];
        out[o+1] = (float)er[tt[1]];
        out[o+2] = (float)er[tt[2]];
    } else {
        size_t o = vbase + ((size_t)g_n1 + 2*(size_t)s2) * 3;
#pragma unroll
        for (int q = 0; q < 6; ++q)
            out[o+q] = (float)er[tt[q]];
    }
}

// ---------------- launch ----------------
extern "C" void kernel_launch(void* const* d_in, const int* in_sizes, int n_in,
                              void* d_out, int out_size)
{
    const float* feats  = (const float*)d_in[0];
    const float* sdf_n  = (const float*)d_in[1];
    const float* dir    = (const float*)d_in[2];
    const float* rotm   = (const float*)d_in[3];
    const float* scales = (const float*)d_in[4];

    int N = in_sizes[1];
    int S = 1;
    while ((long long)S*S*S < (long long)N) ++S;   // S = R+1
    int R = S - 1;
    int E = 7*N;
    int T = 6*R*R*R;
    int NC = R*R*R;
    int NG = (N + 31) >> 5;
    int nCh = (T + TCH - 1) / TCH;
    float dscale = 4.0f / (float)R;
    float* out = (float*)d_out;

    int ngrp = (NC > NG) ? NC : NG;

    k_prep <<<(N + 255)/256, 256>>>(sdf_n, dir, rotm, scales, N, dscale);
    k_grp  <<<(ngrp + 255)/256, 256>>>(N, S, NG, NC, R);
    k_tscan<<<nCh, SCAN_B>>>(T, R, nCh);
    k_emit <<<(E + T + 255)/256, 256>>>(feats, out, E, T, R, S);
}